// round 1
// baseline (speedup 1.0000x reference)
#include <cuda_runtime.h>
#include <cuda_bf16.h>
#include <math.h>
#include <math_constants.h>

// Problem constants
#define BD   2            // batch
#define SD   2048         // seq
#define DD   1024         // model dim
#define HD   16           // heads
#define DKD  64           // head dim
#define HID  4            // indexer heads
#define DID  64           // indexer dim
#define KTOP 512          // top-k
#define ROWS (BD*SD)      // 4096

// ---------------- scratch (device globals; no allocation allowed) ----------------
__device__ float g_qkv[(size_t)ROWS * 3 * DD];     // (b,s,3,H,DK) 50 MB
__device__ float g_qi [(size_t)ROWS * HID * DID];  // 4 MB
__device__ float g_ki [(size_t)ROWS * DID];        // 1 MB
__device__ float g_wi [(size_t)ROWS * HID];
__device__ unsigned short g_topidx[(size_t)ROWS * KTOP]; // 4 MB
__device__ float g_attn[(size_t)ROWS * DD];        // 16 MB

// ---------------- generic SGEMM: C[M,N] = A[M,K] * B[N,K]^T ----------------
// 64x64 tile, BK=16, 256 threads, 4x4 micro-tile
__global__ void gemm_nt(const float* __restrict__ A, const float* __restrict__ B,
                        float* __restrict__ C, int M, int N, int Kd) {
    __shared__ float As[16][65];
    __shared__ float Bs[16][65];
    int tid = threadIdx.x;
    int tx = tid & 15, ty = tid >> 4;
    int bm = blockIdx.y * 64, bn = blockIdx.x * 64;
    float acc[4][4] = {};
    for (int k0 = 0; k0 < Kd; k0 += 16) {
        #pragma unroll
        for (int i = 0; i < 4; i++) {
            int idx = tid + i * 256;
            int m = idx >> 4, k = idx & 15;
            int gm = bm + m;
            As[k][m] = (gm < M) ? A[(size_t)gm * Kd + k0 + k] : 0.0f;
            int gn = bn + m;
            Bs[k][m] = (gn < N) ? B[(size_t)gn * Kd + k0 + k] : 0.0f;
        }
        __syncthreads();
        #pragma unroll
        for (int k = 0; k < 16; k++) {
            float a[4], b[4];
            #pragma unroll
            for (int i = 0; i < 4; i++) a[i] = As[k][ty * 4 + i];
            #pragma unroll
            for (int j = 0; j < 4; j++) b[j] = Bs[k][tx * 4 + j];
            #pragma unroll
            for (int i = 0; i < 4; i++)
                #pragma unroll
                for (int j = 0; j < 4; j++)
                    acc[i][j] = fmaf(a[i], b[j], acc[i][j]);
        }
        __syncthreads();
    }
    #pragma unroll
    for (int i = 0; i < 4; i++) {
        int gm = bm + ty * 4 + i;
        if (gm < M)
            #pragma unroll
            for (int j = 0; j < 4; j++) {
                int gn = bn + tx * 4 + j;
                if (gn < N) C[(size_t)gm * N + gn] = acc[i][j];
            }
    }
}

// ---------------- RoPE on q and k slices of qkv ----------------
// qkv layout per row: [q(0..1023) | k(1024..2047) | v(2048..3071)], head-major, DK=64
__global__ void rope_kernel(float* __restrict__ qkv) {
    int idx = blockIdx.x * blockDim.x + threadIdx.x;  // over ROWS*H*32
    if (idx >= ROWS * HD * 32) return;
    int i  = idx & 31;
    int h  = (idx >> 5) & 15;
    int ts = idx >> 9;          // b*S + t
    int t  = ts & (SD - 1);
    // match jax fp32 inv_freq: compute in double, truncate to fp32
    float inv = (float)(1.0 / pow(10000.0, (double)(2 * i) / 64.0));
    float ang = (float)t * inv;
    float c = cosf(ang), s = sinf(ang);
    size_t base = (size_t)ts * 3072 + h * 64 + 2 * i;
    float x1 = qkv[base], x2 = qkv[base + 1];
    qkv[base]     = x1 * c - x2 * s;
    qkv[base + 1] = x1 * s + x2 * c;
    x1 = qkv[base + 1024]; x2 = qkv[base + 1025];
    qkv[base + 1024] = x1 * c - x2 * s;
    qkv[base + 1025] = x1 * s + x2 * c;
}

// order-preserving float -> uint key (descending select = larger key)
__device__ __forceinline__ unsigned int fkey(float f) {
    unsigned int u = __float_as_uint(f);
    return (u & 0x80000000u) ? ~u : (u | 0x80000000u);
}

// ---------------- indexer scores + exact jax top-k per query row ----------------
// one block per (b,t); 256 threads
__global__ void indexer_topk(const float* __restrict__ qi, const float* __restrict__ ki,
                             const float* __restrict__ wi, unsigned short* __restrict__ topidx) {
    int r = blockIdx.x;
    int b = r >> 11;
    int t = r & (SD - 1);
    int tid = threadIdx.x;
    __shared__ float sc[SD];
    __shared__ float qis[HID * DID];
    __shared__ float wis[HID];
    __shared__ unsigned int hist[256];
    __shared__ unsigned int scanbuf[256];
    __shared__ unsigned int sh_prefix, sh_kneed, sh_outcnt;

    qis[tid] = qi[(size_t)r * 256 + tid];
    if (tid < 4) wis[tid] = wi[r * 4 + tid];
    if (tid == 0) { sh_prefix = 0u; sh_kneed = KTOP; sh_outcnt = 0u; }
    __syncthreads();

    const float* kbase = ki + (size_t)b * SD * DID;
    for (int rr = 0; rr < 8; rr++) {
        int s = tid + rr * 256;
        float val;
        if (s > t) {
            val = -CUDART_INF_F;
        } else {
            const float* kp = kbase + (size_t)s * DID;
            float d0 = 0, d1 = 0, d2 = 0, d3 = 0;
            #pragma unroll
            for (int d = 0; d < 64; d++) {
                float kv = kp[d];
                d0 = fmaf(qis[d],       kv, d0);
                d1 = fmaf(qis[64 + d],  kv, d1);
                d2 = fmaf(qis[128 + d], kv, d2);
                d3 = fmaf(qis[192 + d], kv, d3);
            }
            val = fmaxf(d0, 0.f) * wis[0] + fmaxf(d1, 0.f) * wis[1]
                + fmaxf(d2, 0.f) * wis[2] + fmaxf(d3, 0.f) * wis[3];
            val += 0.0f;   // canonicalize -0.0 -> +0.0 (XLA comparator ties)
        }
        sc[s] = val;
    }
    __syncthreads();

    // MSD radix select (descending) for the 512th-largest key
    unsigned int prefix = 0, maskdone = 0;
    for (int shift = 24; shift >= 0; shift -= 8) {
        hist[tid] = 0;
        __syncthreads();
        for (int rr = 0; rr < 8; rr++) {
            int s = tid * 8 + rr;
            unsigned int key = fkey(sc[s]);
            if ((key & maskdone) == prefix) atomicAdd(&hist[(key >> shift) & 255], 1u);
        }
        __syncthreads();
        if (tid == 0) {
            unsigned int kneed = sh_kneed, c = 0;
            int bsel = 0;
            for (int bb = 255; bb >= 0; bb--) {
                unsigned int c2 = c + hist[bb];
                if (c2 >= kneed) { bsel = bb; break; }
                c = c2;
            }
            sh_kneed  = kneed - c;
            sh_prefix = sh_prefix | ((unsigned int)bsel << shift);
        }
        __syncthreads();
        prefix = sh_prefix;
        maskdone |= (255u << shift);
    }
    unsigned int T    = prefix;
    unsigned int n_eq = sh_kneed;   // how many ties at T to take (lowest index first)

    // count ties in my contiguous chunk, block exclusive-scan for global rank
    unsigned int eqc = 0;
    for (int rr = 0; rr < 8; rr++) {
        int s = tid * 8 + rr;
        if (fkey(sc[s]) == T) eqc++;
    }
    scanbuf[tid] = eqc;
    __syncthreads();
    for (int off = 1; off < 256; off <<= 1) {
        unsigned int v = scanbuf[tid];
        unsigned int add = (tid >= off) ? scanbuf[tid - off] : 0u;
        __syncthreads();
        scanbuf[tid] = v + add;
        __syncthreads();
    }
    unsigned int rank = scanbuf[tid] - eqc;  // exclusive prefix (index-ordered)

    unsigned short* outp = topidx + (size_t)r * KTOP;
    for (int rr = 0; rr < 8; rr++) {
        int s = tid * 8 + rr;
        unsigned int key = fkey(sc[s]);
        if (key > T) {
            unsigned int p = atomicAdd(&sh_outcnt, 1u);
            outp[p] = (unsigned short)s;
        } else if (key == T) {
            if (rank < n_eq) {
                unsigned int p = atomicAdd(&sh_outcnt, 1u);
                outp[p] = (unsigned short)s;
            }
            rank++;
        }
    }
}

// ---------------- gathered sparse attention ----------------
// one block per (head, b*S+t); 128 threads
__global__ void attn_kernel(const float* __restrict__ qkv,
                            const unsigned short* __restrict__ topidx,
                            float* __restrict__ attn_out) {
    int h   = blockIdx.x;
    int row = blockIdx.y;        // b*S + t
    int b   = row >> 11;
    int tid = threadIdx.x;

    __shared__ float q[64];
    __shared__ float sc[KTOP];
    __shared__ int   sidx[KTOP];
    __shared__ float red[4];
    __shared__ float redsum[4];
    __shared__ float part[128];

    const unsigned short* ip = topidx + (size_t)row * KTOP;
    #pragma unroll
    for (int r = 0; r < 4; r++) sidx[tid + 128 * r] = (int)ip[tid + 128 * r];
    if (tid < 64) q[tid] = qkv[(size_t)row * 3072 + h * 64 + tid];
    __syncthreads();

    const float* kb = qkv + (size_t)b * SD * 3072 + 1024 + h * 64;
    float mloc = -CUDART_INF_F;
    #pragma unroll
    for (int r = 0; r < 4; r++) {
        int j = tid + 128 * r;
        const float* kp = kb + (size_t)sidx[j] * 3072;
        float d = 0.f;
        #pragma unroll
        for (int dd = 0; dd < 64; dd++) d = fmaf(q[dd], kp[dd], d);
        d *= 0.125f;   // 1/sqrt(64)
        sc[j] = d;
        mloc = fmaxf(mloc, d);
    }
    for (int o = 16; o; o >>= 1) mloc = fmaxf(mloc, __shfl_xor_sync(0xffffffffu, mloc, o));
    if ((tid & 31) == 0) red[tid >> 5] = mloc;
    __syncthreads();
    float m = fmaxf(fmaxf(red[0], red[1]), fmaxf(red[2], red[3]));

    float sloc = 0.f;
    #pragma unroll
    for (int r = 0; r < 4; r++) {
        int j = tid + 128 * r;
        float e = expf(sc[j] - m);
        sc[j] = e;
        sloc += e;
    }
    for (int o = 16; o; o >>= 1) sloc += __shfl_xor_sync(0xffffffffu, sloc, o);
    if ((tid & 31) == 0) redsum[tid >> 5] = sloc;
    __syncthreads();
    float inv = 1.0f / (redsum[0] + redsum[1] + redsum[2] + redsum[3]);

    int d    = tid & 63;
    int half = tid >> 6;
    const float* vb = qkv + (size_t)b * SD * 3072 + 2048 + h * 64 + d;
    float acc = 0.f;
    int j0 = half * 256;
    for (int j = j0; j < j0 + 256; j++)
        acc = fmaf(sc[j], vb[(size_t)sidx[j] * 3072], acc);
    part[tid] = acc;
    __syncthreads();
    if (tid < 64) {
        float o = (part[tid] + part[tid + 64]) * inv;
        attn_out[(size_t)row * DD + h * 64 + tid] = o;
    }
}

// ---------------- launch ----------------
extern "C" void kernel_launch(void* const* d_in, const int* in_sizes, int n_in,
                              void* d_out, int out_size) {
    const float* x     = (const float*)d_in[0];
    const float* w_qkv = (const float*)d_in[1];
    const float* w_o   = (const float*)d_in[2];
    const float* w_qi  = (const float*)d_in[3];
    const float* w_ki  = (const float*)d_in[4];
    const float* w_wi  = (const float*)d_in[5];
    float* out = (float*)d_out;

    void *p_qkv, *p_qi, *p_ki, *p_wi, *p_top, *p_attn;
    cudaGetSymbolAddress(&p_qkv,  g_qkv);
    cudaGetSymbolAddress(&p_qi,   g_qi);
    cudaGetSymbolAddress(&p_ki,   g_ki);
    cudaGetSymbolAddress(&p_wi,   g_wi);
    cudaGetSymbolAddress(&p_top,  g_topidx);
    cudaGetSymbolAddress(&p_attn, g_attn);

    // 1) projections
    gemm_nt<<<dim3(3 * DD / 64, ROWS / 64), 256>>>(x, w_qkv, (float*)p_qkv, ROWS, 3 * DD, DD);
    gemm_nt<<<dim3((HID * DID) / 64, ROWS / 64), 256>>>(x, w_qi, (float*)p_qi, ROWS, HID * DID, DD);
    gemm_nt<<<dim3(1, ROWS / 64), 256>>>(x, w_ki, (float*)p_ki, ROWS, DID, DD);
    gemm_nt<<<dim3(1, ROWS / 64), 256>>>(x, w_wi, (float*)p_wi, ROWS, HID, DD);

    // 2) RoPE on q,k
    int rope_total = ROWS * HD * 32;
    rope_kernel<<<(rope_total + 255) / 256, 256>>>((float*)p_qkv);

    // 3) indexer scores + exact top-k
    indexer_topk<<<ROWS, 256>>>((const float*)p_qi, (const float*)p_ki,
                                (const float*)p_wi, (unsigned short*)p_top);

    // 4) gathered sparse attention
    attn_kernel<<<dim3(HD, ROWS), 128>>>((const float*)p_qkv,
                                         (const unsigned short*)p_top, (float*)p_attn);

    // 5) output projection
    gemm_nt<<<dim3(DD / 64, ROWS / 64), 256>>>((const float*)p_attn, w_o, out, ROWS, DD, DD);
}

// round 3
// speedup vs baseline: 3.2414x; 3.2414x over previous
#include <cuda_runtime.h>
#include <cuda_bf16.h>
#include <math.h>
#include <math_constants.h>

#define BD   2
#define SD   2048
#define DD   1024
#define HD   16
#define DKD  64
#define HID  4
#define DID  64
#define KTOP 512
#define ROWS (BD*SD)

// ---------------- scratch ----------------
__device__ float g_qkv[(size_t)ROWS * 3 * DD];
__device__ float g_qi [(size_t)ROWS * HID * DID];
__device__ float g_ki [(size_t)ROWS * DID];
__device__ float g_wi [(size_t)ROWS * HID];
__device__ unsigned short g_topidx[(size_t)ROWS * KTOP];
__device__ float g_attn[(size_t)ROWS * DD];

// ---------------- big SGEMM: C[M,N] = A[M,K]*B[N,K]^T, 128x128x16, 8x8 micro ----------------
// requires M%128==0, N%128==0, K%16==0
__global__ __launch_bounds__(256) void gemm_nt_128(
    const float* __restrict__ A, const float* __restrict__ B,
    float* __restrict__ C, int M, int N, int Kd)
{
    __shared__ __align__(16) float As[16][132];
    __shared__ __align__(16) float Bs[16][132];
    int tid = threadIdx.x;
    int bm = blockIdx.y * 128, bn = blockIdx.x * 128;
    int lr = tid >> 2;           // 0..63
    int lk = (tid & 3) * 4;      // 0,4,8,12
    int tx = tid & 15, ty = tid >> 4;
    float acc[8][8] = {};
    const float* Abase = A + (size_t)bm * Kd + lk;
    const float* Bbase = B + (size_t)bn * Kd + lk;
    for (int k0 = 0; k0 < Kd; k0 += 16) {
        #pragma unroll
        for (int half = 0; half < 2; half++) {
            int m = lr + half * 64;
            float4 av = *(const float4*)(Abase + (size_t)m * Kd + k0);
            As[lk + 0][m] = av.x; As[lk + 1][m] = av.y;
            As[lk + 2][m] = av.z; As[lk + 3][m] = av.w;
            float4 bv = *(const float4*)(Bbase + (size_t)m * Kd + k0);
            Bs[lk + 0][m] = bv.x; Bs[lk + 1][m] = bv.y;
            Bs[lk + 2][m] = bv.z; Bs[lk + 3][m] = bv.w;
        }
        __syncthreads();
        #pragma unroll
        for (int k = 0; k < 16; k++) {
            float a[8], b[8];
            *(float4*)&a[0] = *(const float4*)&As[k][ty * 8];
            *(float4*)&a[4] = *(const float4*)&As[k][ty * 8 + 4];
            *(float4*)&b[0] = *(const float4*)&Bs[k][tx * 8];
            *(float4*)&b[4] = *(const float4*)&Bs[k][tx * 8 + 4];
            #pragma unroll
            for (int i = 0; i < 8; i++)
                #pragma unroll
                for (int j = 0; j < 8; j++)
                    acc[i][j] = fmaf(a[i], b[j], acc[i][j]);
        }
        __syncthreads();
    }
    #pragma unroll
    for (int i = 0; i < 8; i++) {
        size_t rowoff = (size_t)(bm + ty * 8 + i) * N + bn + tx * 8;
        float4 v0 = make_float4(acc[i][0], acc[i][1], acc[i][2], acc[i][3]);
        float4 v1 = make_float4(acc[i][4], acc[i][5], acc[i][6], acc[i][7]);
        *(float4*)&C[rowoff]     = v0;
        *(float4*)&C[rowoff + 4] = v1;
    }
}

// ---------------- small fused SGEMM (qi, ki, wi in one launch) ----------------
// 64x64 tile, 4x4 micro; blockIdx.z selects which projection
__global__ void gemm_small_fused(const float* __restrict__ A,
                                 const float* __restrict__ B0, const float* __restrict__ B1,
                                 const float* __restrict__ B2,
                                 float* __restrict__ C0, float* __restrict__ C1,
                                 float* __restrict__ C2, int M, int Kd)
{
    const float* B; float* C; int N;
    if (blockIdx.z == 0)      { B = B0; C = C0; N = 256; }   // qi: HI*DI
    else if (blockIdx.z == 1) { B = B1; C = C1; N = 64;  }   // ki: DI
    else                      { B = B2; C = C2; N = 4;   }   // wi: HI   (was 16 -> BUG)
    int bn = blockIdx.x * 64;
    if (bn >= N) return;

    __shared__ float As[16][65];
    __shared__ float Bs[16][65];
    int tid = threadIdx.x;
    int tx = tid & 15, ty = tid >> 4;
    int bm = blockIdx.y * 64;
    float acc[4][4] = {};
    for (int k0 = 0; k0 < Kd; k0 += 16) {
        #pragma unroll
        for (int i = 0; i < 4; i++) {
            int idx = tid + i * 256;
            int m = idx >> 4, k = idx & 15;
            As[k][m] = A[(size_t)(bm + m) * Kd + k0 + k];
            int gn = bn + m;
            Bs[k][m] = (gn < N) ? B[(size_t)gn * Kd + k0 + k] : 0.0f;
        }
        __syncthreads();
        #pragma unroll
        for (int k = 0; k < 16; k++) {
            float a[4], b[4];
            #pragma unroll
            for (int i = 0; i < 4; i++) a[i] = As[k][ty * 4 + i];
            #pragma unroll
            for (int j = 0; j < 4; j++) b[j] = Bs[k][tx * 4 + j];
            #pragma unroll
            for (int i = 0; i < 4; i++)
                #pragma unroll
                for (int j = 0; j < 4; j++)
                    acc[i][j] = fmaf(a[i], b[j], acc[i][j]);
        }
        __syncthreads();
    }
    #pragma unroll
    for (int i = 0; i < 4; i++) {
        int gm = bm + ty * 4 + i;
        #pragma unroll
        for (int j = 0; j < 4; j++) {
            int gn = bn + tx * 4 + j;
            if (gn < N) C[(size_t)gm * N + gn] = acc[i][j];
        }
    }
}

// ---------------- RoPE ----------------
__global__ void rope_kernel(float* __restrict__ qkv) {
    int idx = blockIdx.x * blockDim.x + threadIdx.x;
    if (idx >= ROWS * HD * 32) return;
    int i  = idx & 31;
    int h  = (idx >> 5) & 15;
    int ts = idx >> 9;
    int t  = ts & (SD - 1);
    float inv = (float)(1.0 / pow(10000.0, (double)(2 * i) / 64.0));
    float ang = (float)t * inv;
    float c = cosf(ang), s = sinf(ang);
    size_t base = (size_t)ts * 3072 + h * 64 + 2 * i;
    float x1 = qkv[base], x2 = qkv[base + 1];
    qkv[base]     = x1 * c - x2 * s;
    qkv[base + 1] = x1 * s + x2 * c;
    x1 = qkv[base + 1024]; x2 = qkv[base + 1025];
    qkv[base + 1024] = x1 * c - x2 * s;
    qkv[base + 1025] = x1 * s + x2 * c;
}

__device__ __forceinline__ unsigned int fkey(float f) {
    unsigned int u = __float_as_uint(f);
    return (u & 0x80000000u) ? ~u : (u | 0x80000000u);
}

// ---------------- indexer + exact top-k ----------------
__global__ void indexer_topk(const float* __restrict__ qi, const float* __restrict__ ki,
                             const float* __restrict__ wi, unsigned short* __restrict__ topidx) {
    int r = blockIdx.x;
    int b = r >> 11;
    int t = r & (SD - 1);
    int tid = threadIdx.x;
    __shared__ float sc[SD];
    __shared__ __align__(16) float qis[HID * DID];
    __shared__ float wis[HID];
    __shared__ unsigned int hist[256];
    __shared__ unsigned int scanbuf[256];
    __shared__ unsigned int sh_prefix, sh_kneed, sh_outcnt;

    qis[tid] = qi[(size_t)r * 256 + tid];
    if (tid < 4) wis[tid] = wi[r * 4 + tid];
    if (tid == 0) { sh_prefix = 0u; sh_kneed = KTOP; sh_outcnt = 0u; }
    __syncthreads();

    const float* kbase = ki + (size_t)b * SD * DID;
    const float4* q4 = (const float4*)qis;
    for (int rr = 0; rr < 8; rr++) {
        int s = tid + rr * 256;
        float val;
        if (s > t) {
            val = -CUDART_INF_F;
        } else {
            const float4* kp4 = (const float4*)(kbase + (size_t)s * DID);
            float d0 = 0, d1 = 0, d2 = 0, d3 = 0;
            #pragma unroll
            for (int d4 = 0; d4 < 16; d4++) {
                float4 kv = kp4[d4];
                float4 a0 = q4[d4], a1 = q4[16 + d4], a2 = q4[32 + d4], a3 = q4[48 + d4];
                d0 = fmaf(a0.x, kv.x, d0); d0 = fmaf(a0.y, kv.y, d0);
                d0 = fmaf(a0.z, kv.z, d0); d0 = fmaf(a0.w, kv.w, d0);
                d1 = fmaf(a1.x, kv.x, d1); d1 = fmaf(a1.y, kv.y, d1);
                d1 = fmaf(a1.z, kv.z, d1); d1 = fmaf(a1.w, kv.w, d1);
                d2 = fmaf(a2.x, kv.x, d2); d2 = fmaf(a2.y, kv.y, d2);
                d2 = fmaf(a2.z, kv.z, d2); d2 = fmaf(a2.w, kv.w, d2);
                d3 = fmaf(a3.x, kv.x, d3); d3 = fmaf(a3.y, kv.y, d3);
                d3 = fmaf(a3.z, kv.z, d3); d3 = fmaf(a3.w, kv.w, d3);
            }
            val = fmaxf(d0, 0.f) * wis[0] + fmaxf(d1, 0.f) * wis[1]
                + fmaxf(d2, 0.f) * wis[2] + fmaxf(d3, 0.f) * wis[3];
            val += 0.0f;
        }
        sc[s] = val;
    }
    __syncthreads();

    unsigned int prefix = 0, maskdone = 0;
    for (int shift = 24; shift >= 0; shift -= 8) {
        hist[tid] = 0;
        __syncthreads();
        for (int rr = 0; rr < 8; rr++) {
            int s = tid * 8 + rr;
            unsigned int key = fkey(sc[s]);
            if ((key & maskdone) == prefix) atomicAdd(&hist[(key >> shift) & 255], 1u);
        }
        __syncthreads();
        if (tid == 0) {
            unsigned int kneed = sh_kneed, c = 0;
            int bsel = 0;
            for (int bb = 255; bb >= 0; bb--) {
                unsigned int c2 = c + hist[bb];
                if (c2 >= kneed) { bsel = bb; break; }
                c = c2;
            }
            sh_kneed  = kneed - c;
            sh_prefix = sh_prefix | ((unsigned int)bsel << shift);
        }
        __syncthreads();
        prefix = sh_prefix;
        maskdone |= (255u << shift);
    }
    unsigned int T    = prefix;
    unsigned int n_eq = sh_kneed;

    unsigned int eqc = 0;
    for (int rr = 0; rr < 8; rr++) {
        int s = tid * 8 + rr;
        if (fkey(sc[s]) == T) eqc++;
    }
    scanbuf[tid] = eqc;
    __syncthreads();
    for (int off = 1; off < 256; off <<= 1) {
        unsigned int v = scanbuf[tid];
        unsigned int add = (tid >= off) ? scanbuf[tid - off] : 0u;
        __syncthreads();
        scanbuf[tid] = v + add;
        __syncthreads();
    }
    unsigned int rank = scanbuf[tid] - eqc;

    unsigned short* outp = topidx + (size_t)r * KTOP;
    for (int rr = 0; rr < 8; rr++) {
        int s = tid * 8 + rr;
        unsigned int key = fkey(sc[s]);
        if (key > T) {
            unsigned int p = atomicAdd(&sh_outcnt, 1u);
            outp[p] = (unsigned short)s;
        } else if (key == T) {
            if (rank < n_eq) {
                unsigned int p = atomicAdd(&sh_outcnt, 1u);
                outp[p] = (unsigned short)s;
            }
            rank++;
        }
    }
}

// ---------------- gathered sparse attention (coalesced warp-per-key scores) ----------------
__global__ void attn_kernel(const float* __restrict__ qkv,
                            const unsigned short* __restrict__ topidx,
                            float* __restrict__ attn_out) {
    int h   = blockIdx.x;
    int row = blockIdx.y;
    int b   = row >> 11;
    int tid  = threadIdx.x;
    int lane = tid & 31, w = tid >> 5;

    __shared__ float q[64];
    __shared__ float sc[KTOP];
    __shared__ int   sidx[KTOP];
    __shared__ float redm[4], redsum[4];
    __shared__ float part[128];

    const unsigned short* ip = topidx + (size_t)row * KTOP;
    #pragma unroll
    for (int r = 0; r < 4; r++) sidx[tid + 128 * r] = (int)ip[tid + 128 * r];
    if (tid < 64) q[tid] = qkv[(size_t)row * 3072 + h * 64 + tid];
    __syncthreads();

    // scores: warp w handles keys [w*128, w*128+128); lane owns 2 dims (float2)
    float qx = q[2 * lane], qy = q[2 * lane + 1];
    const float* kb = qkv + (size_t)b * SD * 3072 + 1024 + h * 64 + 2 * lane;
    float mloc = -CUDART_INF_F;
    int j0 = w * 128;
    for (int jj = 0; jj < 128; jj += 4) {
        int j = j0 + jj;
        float d[4];
        #pragma unroll
        for (int u = 0; u < 4; u++) {
            float2 kv = *(const float2*)(kb + (size_t)sidx[j + u] * 3072);
            d[u] = fmaf(qx, kv.x, qy * kv.y);
        }
        #pragma unroll
        for (int u = 0; u < 4; u++) {
            #pragma unroll
            for (int o = 16; o; o >>= 1) d[u] += __shfl_xor_sync(0xffffffffu, d[u], o);
            d[u] *= 0.125f;
            mloc = fmaxf(mloc, d[u]);
        }
        if (lane < 4) sc[j + lane] = d[lane];
    }
    if (lane == 0) redm[w] = mloc;
    __syncthreads();
    float m = fmaxf(fmaxf(redm[0], redm[1]), fmaxf(redm[2], redm[3]));

    float sloc = 0.f;
    #pragma unroll
    for (int r = 0; r < 4; r++) {
        int j = tid + 128 * r;
        float e = expf(sc[j] - m);
        sc[j] = e;
        sloc += e;
    }
    #pragma unroll
    for (int o = 16; o; o >>= 1) sloc += __shfl_xor_sync(0xffffffffu, sloc, o);
    if (lane == 0) redsum[w] = sloc;
    __syncthreads();
    float inv = 1.0f / (redsum[0] + redsum[1] + redsum[2] + redsum[3]);

    int d    = tid & 63;
    int half = tid >> 6;
    const float* vb = qkv + (size_t)b * SD * 3072 + 2048 + h * 64 + d;
    float acc = 0.f;
    int jb = half * 256;
    #pragma unroll 4
    for (int j = jb; j < jb + 256; j++)
        acc = fmaf(sc[j], vb[(size_t)sidx[j] * 3072], acc);
    part[tid] = acc;
    __syncthreads();
    if (tid < 64)
        attn_out[(size_t)row * DD + h * 64 + tid] = (part[tid] + part[tid + 64]) * inv;
}

// ---------------- launch ----------------
extern "C" void kernel_launch(void* const* d_in, const int* in_sizes, int n_in,
                              void* d_out, int out_size) {
    const float* x     = (const float*)d_in[0];
    const float* w_qkv = (const float*)d_in[1];
    const float* w_o   = (const float*)d_in[2];
    const float* w_qi  = (const float*)d_in[3];
    const float* w_ki  = (const float*)d_in[4];
    const float* w_wi  = (const float*)d_in[5];
    float* out = (float*)d_out;

    void *p_qkv, *p_qi, *p_ki, *p_wi, *p_top, *p_attn;
    cudaGetSymbolAddress(&p_qkv,  g_qkv);
    cudaGetSymbolAddress(&p_qi,   g_qi);
    cudaGetSymbolAddress(&p_ki,   g_ki);
    cudaGetSymbolAddress(&p_wi,   g_wi);
    cudaGetSymbolAddress(&p_top,  g_topidx);
    cudaGetSymbolAddress(&p_attn, g_attn);

    // 1) projections
    gemm_nt_128<<<dim3(3 * DD / 128, ROWS / 128), 256>>>(x, w_qkv, (float*)p_qkv, ROWS, 3 * DD, DD);
    gemm_small_fused<<<dim3(4, ROWS / 64, 3), 256>>>(x, w_qi, w_ki, w_wi,
                                                     (float*)p_qi, (float*)p_ki, (float*)p_wi,
                                                     ROWS, DD);

    // 2) RoPE
    int rope_total = ROWS * HD * 32;
    rope_kernel<<<(rope_total + 255) / 256, 256>>>((float*)p_qkv);

    // 3) indexer + top-k
    indexer_topk<<<ROWS, 256>>>((const float*)p_qi, (const float*)p_ki,
                                (const float*)p_wi, (unsigned short*)p_top);

    // 4) sparse attention
    attn_kernel<<<dim3(HD, ROWS), 128>>>((const float*)p_qkv,
                                         (const unsigned short*)p_top, (float*)p_attn);

    // 5) output projection
    gemm_nt_128<<<dim3(DD / 128, ROWS / 128), 256>>>((const float*)p_attn, w_o, out, ROWS, DD, DD);
}